// round 8
// baseline (speedup 1.0000x reference)
#include <cuda_runtime.h>

// RotationGate: batched RX on qubit 0 (MSB axis) of a 22-qubit state.
// state_re/state_im: (DIM, 16) fp32 row-major; each row = 4 float4.
// out: (2, DIM, 16) fp32 (real plane, imag plane).
//   out0 = c*s0 - i*s*s1 ; out1 = c*s1 - i*s*s0  with c=cos(th/2), s=sin(th/2)
//
// HBM-bound streaming (1.07 GB; floor ~134us at 8TB/s spec). History:
//  R1 prep+main:            main 152.8us (2 graph nodes)
//  R2 fused+barrier+.cs(LD+ST): main 155.8 (conflated: barrier + hints)
//  R4 fused, no-sync, MUFU: main 150.2, DRAM 85.8%
//  R5 MLP=8/thread:         occ 52.8 -> main 152.0 (reverted)
//  R6 tpb=512:              main 150.9 (neutral)
//  R7 store-on-ready:       main 149.5, DRAM 86.0%  <- best
// R8 = R7 + __stcs on the four output streams ONLY (loads stay default-cached;
// R2 never isolated store hints). Total has a fixed ~8us graph overhead.

#define HALF4   8388608    /* (DIM/2)*16/4 float4 per half-plane */
#define IMOFF   16777216   /* DIM*16/4: imag plane offset in float4 */

__global__ __launch_bounds__(256, 8)
void rot_fused_kernel(const float* __restrict__ theta,
                      const float* __restrict__ re_,
                      const float* __restrict__ im_,
                      float* __restrict__ out_) {
    int t = blockIdx.x * 256 + threadIdx.x;   // t in [0, HALF4)
    const float4* __restrict__ re  = (const float4*)re_;
    const float4* __restrict__ im  = (const float4*)im_;
    float4* __restrict__ out = (float4*)out_;

    int g = threadIdx.x & 3;  // batch quad: batches 4g..4g+3
    float4 th = ((const float4*)theta)[g];

    // Front-batch the 4 bulk loads (default cached); MUFU coeff math
    // overlaps the DRAM latency.
    float4 r0 = re[t];
    float4 i0 = im[t];
    float4 r1 = re[t + HALF4];
    float4 i1 = im[t + HALF4];

    float4 c4, s4;
    c4.x = __cosf(th.x * 0.5f);  s4.x = __sinf(th.x * 0.5f);
    c4.y = __cosf(th.y * 0.5f);  s4.y = __sinf(th.y * 0.5f);
    c4.z = __cosf(th.z * 0.5f);  s4.z = __sinf(th.z * 0.5f);
    c4.w = __cosf(th.w * 0.5f);  s4.w = __sinf(th.w * 0.5f);

    float4 o;

    // Store each result as soon as it is ready; evict-first stores keep L2
    // capacity available for the inbound read streams.
    o.x = fmaf(c4.x, r0.x,  s4.x * i1.x);
    o.y = fmaf(c4.y, r0.y,  s4.y * i1.y);
    o.z = fmaf(c4.z, r0.z,  s4.z * i1.z);
    o.w = fmaf(c4.w, r0.w,  s4.w * i1.w);
    __stcs(&out[t], o);

    o.x = fmaf(c4.x, r1.x,  s4.x * i0.x);
    o.y = fmaf(c4.y, r1.y,  s4.y * i0.y);
    o.z = fmaf(c4.z, r1.z,  s4.z * i0.z);
    o.w = fmaf(c4.w, r1.w,  s4.w * i0.w);
    __stcs(&out[t + HALF4], o);

    o.x = fmaf(c4.x, i0.x, -s4.x * r1.x);
    o.y = fmaf(c4.y, i0.y, -s4.y * r1.y);
    o.z = fmaf(c4.z, i0.z, -s4.z * r1.z);
    o.w = fmaf(c4.w, i0.w, -s4.w * r1.w);
    __stcs(&out[t + IMOFF], o);

    o.x = fmaf(c4.x, i1.x, -s4.x * r0.x);
    o.y = fmaf(c4.y, i1.y, -s4.y * r0.y);
    o.z = fmaf(c4.z, i1.z, -s4.z * r0.z);
    o.w = fmaf(c4.w, i1.w, -s4.w * r0.w);
    __stcs(&out[t + IMOFF + HALF4], o);
}

extern "C" void kernel_launch(void* const* d_in, const int* in_sizes, int n_in,
                              void* d_out, int out_size) {
    const float* theta = (const float*)d_in[0];
    const float* s_re  = (const float*)d_in[1];
    const float* s_im  = (const float*)d_in[2];
    float* out = (float*)d_out;

    int tpb    = 256;
    int blocks = HALF4 / tpb;     // 32,768 blocks
    rot_fused_kernel<<<blocks, tpb>>>(theta, s_re, s_im, out);
}

// round 9
// speedup vs baseline: 1.0020x; 1.0020x over previous
#include <cuda_runtime.h>

// RotationGate: batched RX on qubit 0 (MSB axis) of a 22-qubit state.
// state_re/state_im: (DIM, 16) fp32 row-major; each row = 4 float4.
// out: (2, DIM, 16) fp32 (real plane, imag plane).
//   out0 = c*s0 - i*s*s1 ; out1 = c*s1 - i*s*s0  with c=cos(th/2), s=sin(th/2)
//
// HBM-bound streaming, irreducible 1 GiB traffic (floor ~134us @ 8TB/s spec).
// Final configuration after 8 measured rounds:
//  - single fused kernel (separate prep kernel cost +5us graph node overhead)
//  - NO synchronization: each thread computes its 4 (c,s) pairs via MUFU
//    (__cosf/__sinf; args in [0,pi], abs err ~1e-6 << 1e-3 tolerance).
//    A 16-thread+smem+barrier variant gated stores on warp0 -> +3..5us.
//  - 1 float4-group per thread, tpb=256, lb(256,8): MLP=8/thread halved
//    occupancy (regs 43) for zero gain; tpb=512 neutral.
//  - plain cached loads AND stores: .cs hints regressed in every variant
//    (R2 both: +3us; R8 stores-only: +0.8us).
//  - store-on-ready ordering: first STG issues earlier, regs stay at 32.
// Measured: main kernel 149.5us, 6814 GB/s (85.2% spec), DRAM 86.0%,
// occ 78.8%, issue 12.4% -- read/write-turnaround-limited HBM ceiling.

#define HALF4   8388608    /* (DIM/2)*16/4 float4 per half-plane */
#define IMOFF   16777216   /* DIM*16/4: imag plane offset in float4 */

__global__ __launch_bounds__(256, 8)
void rot_fused_kernel(const float* __restrict__ theta,
                      const float* __restrict__ re_,
                      const float* __restrict__ im_,
                      float* __restrict__ out_) {
    int t = blockIdx.x * 256 + threadIdx.x;   // t in [0, HALF4)
    const float4* __restrict__ re  = (const float4*)re_;
    const float4* __restrict__ im  = (const float4*)im_;
    float4* __restrict__ out = (float4*)out_;

    int g = threadIdx.x & 3;  // batch quad: batches 4g..4g+3
    float4 th = ((const float4*)theta)[g];

    // Front-batch the 4 bulk loads; MUFU coeff math overlaps DRAM latency.
    float4 r0 = re[t];
    float4 i0 = im[t];
    float4 r1 = re[t + HALF4];
    float4 i1 = im[t + HALF4];

    float4 c4, s4;
    c4.x = __cosf(th.x * 0.5f);  s4.x = __sinf(th.x * 0.5f);
    c4.y = __cosf(th.y * 0.5f);  s4.y = __sinf(th.y * 0.5f);
    c4.z = __cosf(th.z * 0.5f);  s4.z = __sinf(th.z * 0.5f);
    c4.w = __cosf(th.w * 0.5f);  s4.w = __sinf(th.w * 0.5f);

    float4 o;

    // Store each result as soon as it is ready: first STG issues ~20cy
    // earlier and register live ranges stay short (regs <= 32).
    o.x = fmaf(c4.x, r0.x,  s4.x * i1.x);
    o.y = fmaf(c4.y, r0.y,  s4.y * i1.y);
    o.z = fmaf(c4.z, r0.z,  s4.z * i1.z);
    o.w = fmaf(c4.w, r0.w,  s4.w * i1.w);
    out[t] = o;

    o.x = fmaf(c4.x, r1.x,  s4.x * i0.x);
    o.y = fmaf(c4.y, r1.y,  s4.y * i0.y);
    o.z = fmaf(c4.z, r1.z,  s4.z * i0.z);
    o.w = fmaf(c4.w, r1.w,  s4.w * i0.w);
    out[t + HALF4] = o;

    o.x = fmaf(c4.x, i0.x, -s4.x * r1.x);
    o.y = fmaf(c4.y, i0.y, -s4.y * r1.y);
    o.z = fmaf(c4.z, i0.z, -s4.z * r1.z);
    o.w = fmaf(c4.w, i0.w, -s4.w * r1.w);
    out[t + IMOFF] = o;

    o.x = fmaf(c4.x, i1.x, -s4.x * r0.x);
    o.y = fmaf(c4.y, i1.y, -s4.y * r0.y);
    o.z = fmaf(c4.z, i1.z, -s4.z * r0.z);
    o.w = fmaf(c4.w, i1.w, -s4.w * r0.w);
    out[t + IMOFF + HALF4] = o;
}

extern "C" void kernel_launch(void* const* d_in, const int* in_sizes, int n_in,
                              void* d_out, int out_size) {
    const float* theta = (const float*)d_in[0];
    const float* s_re  = (const float*)d_in[1];
    const float* s_im  = (const float*)d_in[2];
    float* out = (float*)d_out;

    int tpb    = 256;
    int blocks = HALF4 / tpb;     // 32,768 blocks
    rot_fused_kernel<<<blocks, tpb>>>(theta, s_re, s_im, out);
}

// round 10
// speedup vs baseline: 1.0043x; 1.0022x over previous
#include <cuda_runtime.h>

// RotationGate: batched RX on qubit 0 (MSB axis) of a 22-qubit state.
// state_re/state_im: (DIM, 16) fp32 row-major; each row = 4 float4.
// out: (2, DIM, 16) fp32 (real plane, imag plane).
//   out0 = c*s0 - i*s*s1 ; out1 = c*s1 - i*s*s0  with c=cos(th/2), s=sin(th/2)
//
// HBM-bound streaming, irreducible 1 GiB traffic (floor ~134us @ 8TB/s spec).
// Measured plateau (R7/R9 identical source): main 149.5-150.4us,
// 6.78-6.81 TB/s (85% spec), DRAM 85.5-86.0%, noise +-0.5us.
// Settled by experiment:
//  - single fused kernel, NO sync: per-thread MUFU coeffs (__cosf/__sinf,
//    args in [0,pi], abs err ~1e-6 << 1e-3). Barrier variants cost +3..5us.
//  - 1 float4-group/thread: MLP=8 halved occupancy (regs 43) for zero gain.
//  - plain cached loads AND stores: every .cs variant regressed.
//  - store-on-ready ordering; regs=32.
// R10: only untested axis -- tpb=128 (finer wave granularity / smaller
// per-CTA LDG burst at L1tex, shorter final-wave tail). Everything else R7.

#define HALF4   8388608    /* (DIM/2)*16/4 float4 per half-plane */
#define IMOFF   16777216   /* DIM*16/4: imag plane offset in float4 */

__global__ __launch_bounds__(128, 16)
void rot_fused_kernel(const float* __restrict__ theta,
                      const float* __restrict__ re_,
                      const float* __restrict__ im_,
                      float* __restrict__ out_) {
    int t = blockIdx.x * 128 + threadIdx.x;   // t in [0, HALF4)
    const float4* __restrict__ re  = (const float4*)re_;
    const float4* __restrict__ im  = (const float4*)im_;
    float4* __restrict__ out = (float4*)out_;

    int g = threadIdx.x & 3;  // batch quad: batches 4g..4g+3
    float4 th = ((const float4*)theta)[g];

    // Front-batch the 4 bulk loads; MUFU coeff math overlaps DRAM latency.
    float4 r0 = re[t];
    float4 i0 = im[t];
    float4 r1 = re[t + HALF4];
    float4 i1 = im[t + HALF4];

    float4 c4, s4;
    c4.x = __cosf(th.x * 0.5f);  s4.x = __sinf(th.x * 0.5f);
    c4.y = __cosf(th.y * 0.5f);  s4.y = __sinf(th.y * 0.5f);
    c4.z = __cosf(th.z * 0.5f);  s4.z = __sinf(th.z * 0.5f);
    c4.w = __cosf(th.w * 0.5f);  s4.w = __sinf(th.w * 0.5f);

    float4 o;

    // Store each result as soon as it is ready.
    o.x = fmaf(c4.x, r0.x,  s4.x * i1.x);
    o.y = fmaf(c4.y, r0.y,  s4.y * i1.y);
    o.z = fmaf(c4.z, r0.z,  s4.z * i1.z);
    o.w = fmaf(c4.w, r0.w,  s4.w * i1.w);
    out[t] = o;

    o.x = fmaf(c4.x, r1.x,  s4.x * i0.x);
    o.y = fmaf(c4.y, r1.y,  s4.y * i0.y);
    o.z = fmaf(c4.z, r1.z,  s4.z * i0.z);
    o.w = fmaf(c4.w, r1.w,  s4.w * i0.w);
    out[t + HALF4] = o;

    o.x = fmaf(c4.x, i0.x, -s4.x * r1.x);
    o.y = fmaf(c4.y, i0.y, -s4.y * r1.y);
    o.z = fmaf(c4.z, i0.z, -s4.z * r1.z);
    o.w = fmaf(c4.w, i0.w, -s4.w * r1.w);
    out[t + IMOFF] = o;

    o.x = fmaf(c4.x, i1.x, -s4.x * r0.x);
    o.y = fmaf(c4.y, i1.y, -s4.y * r0.y);
    o.z = fmaf(c4.z, i1.z, -s4.z * r0.z);
    o.w = fmaf(c4.w, i1.w, -s4.w * r0.w);
    out[t + IMOFF + HALF4] = o;
}

extern "C" void kernel_launch(void* const* d_in, const int* in_sizes, int n_in,
                              void* d_out, int out_size) {
    const float* theta = (const float*)d_in[0];
    const float* s_re  = (const float*)d_in[1];
    const float* s_im  = (const float*)d_in[2];
    float* out = (float*)d_out;

    int tpb    = 128;
    int blocks = HALF4 / tpb;     // 65,536 blocks
    rot_fused_kernel<<<blocks, tpb>>>(theta, s_re, s_im, out);
}